// round 4
// baseline (speedup 1.0000x reference)
#include <cuda_runtime.h>
#include <cstdint>

#define OMEGA 30.0f
#define HID 128
#define MROW 256          // points per CTA
#define THREADS 512
#define NPTS 2048
#define NCHUNK (NPTS / MROW)

// shared memory layout (in floats)
#define HT_SZ   (HID * MROW)          // 32768
#define WS_SZ   (HID * HID)           // 16384
#define SMEM_FLOATS (HT_SZ + WS_SZ + 4*256 + 128)
#define SMEM_BYTES  (SMEM_FLOATS * 4)

// ---------------- packed f32x2 helpers ----------------
__device__ __forceinline__ uint64_t pack2(float lo, float hi) {
    uint64_t r;
    asm("mov.b64 %0, {%1, %2};" : "=l"(r) : "f"(lo), "f"(hi));
    return r;
}
__device__ __forceinline__ float2 unpack2(uint64_t v) {
    float2 f;
    asm("mov.b64 {%0, %1}, %2;" : "=f"(f.x), "=f"(f.y) : "l"(v));
    return f;
}
__device__ __forceinline__ uint64_t fma2(uint64_t a, uint64_t b, uint64_t c) {
    uint64_t d;
    asm("fma.rn.f32x2 %0, %1, %2, %3;" : "=l"(d) : "l"(a), "l"(b), "l"(c));
    return d;
}

// ---------------- accurate fast sin ----------------
// |x| < ~600 here. Reduce by pi (2-term Cody-Waite), deg-11 odd minimax poly
// (valid on [-pi/2,pi/2] after rintf reduction), sign flip by parity of k.
// Abs err ~1e-7.
__device__ __forceinline__ float fast_sin(float x) {
    float k = rintf(x * 0.3183098861837907f);
    float r = fmaf(k, -3.14159274f, x);
    r = fmaf(k, 8.742277657e-8f, r);
    float y = r * r;
    float p = fmaf(y, -2.3889859e-8f, 2.7525562e-6f);
    p = fmaf(y, p, -1.9840874e-4f);
    p = fmaf(y, p, 8.3333310e-3f);
    p = fmaf(y, p, -1.6666667e-1f);
    p = fmaf(y, p, 1.0f);
    p = r * p;
    int ki = (int)k;
    return __int_as_float(__float_as_int(p) ^ ((ki & 1) << 31));
}

// ---------------- codebook dequant into smem ----------------
__device__ __forceinline__ void dequant(float* Ws, const int* labels,
                                        const float* cent, int n4, int tid) {
    const int4* lb = (const int4*)labels;
    float4* w4 = (float4*)Ws;
    for (int i = tid; i < n4; i += THREADS) {
        int4 v = lb[i];
        float4 w;
        w.x = cent[v.x]; w.y = cent[v.y]; w.z = cent[v.z]; w.w = cent[v.w];
        w4[i] = w;
    }
}

// ---------------- one hidden layer: hT(new) = sin(OMEGA*(hT @ Ws + bias)) ----
// hT: [K rows][MROW pts], Ws: [K rows][HID cols]. Thread tile 8 pts x 8 outs.
// Contains ONE internal __syncthreads between reads (gemm+bias) and writes.
template<int K>
__device__ __forceinline__ void layer_gemm_sin(float* hT, const float* Ws,
                                               const float* bias_s,
                                               int tm, int tn) {
    uint64_t acc[8][4];
#pragma unroll
    for (int i = 0; i < 8; i++)
#pragma unroll
        for (int j = 0; j < 4; j++) acc[i][j] = 0ULL;

    const float4* hp = (const float4*)hT;
    const float4* wp = (const float4*)Ws;
#pragma unroll 8
    for (int k = 0; k < K; k++) {
        float4 A0 = hp[k * (MROW / 4) + tm];
        float4 A1 = hp[k * (MROW / 4) + 32 + tm];
        float4 B0 = wp[k * (HID / 4) + tn];
        float4 B1 = wp[k * (HID / 4) + 16 + tn];
        uint64_t b0 = pack2(B0.x, B0.y);
        uint64_t b1 = pack2(B0.z, B0.w);
        uint64_t b2 = pack2(B1.x, B1.y);
        uint64_t b3 = pack2(B1.z, B1.w);
        float am[8] = {A0.x, A0.y, A0.z, A0.w, A1.x, A1.y, A1.z, A1.w};
#pragma unroll
        for (int mi = 0; mi < 8; mi++) {
            uint64_t a2 = pack2(am[mi], am[mi]);
            acc[mi][0] = fma2(a2, b0, acc[mi][0]);
            acc[mi][1] = fma2(a2, b1, acc[mi][1]);
            acc[mi][2] = fma2(a2, b2, acc[mi][2]);
            acc[mi][3] = fma2(a2, b3, acc[mi][3]);
        }
    }

    // bias add (reads bias_s BEFORE the sync so caller may overwrite it after)
    float av[8][8];
#pragma unroll
    for (int p = 0; p < 4; p++) {
        int nb = (p < 2) ? (tn * 4 + 2 * p) : (64 + tn * 4 + 2 * (p - 2));
        float bx = bias_s[nb];
        float by = bias_s[nb + 1];
#pragma unroll
        for (int mi = 0; mi < 8; mi++) {
            float2 v = unpack2(acc[mi][p]);
            av[mi][2 * p]     = v.x + bx;
            av[mi][2 * p + 1] = v.y + by;
        }
    }
    __syncthreads();   // all reads of hT/Ws/bias_s complete

    // sin + writeback into hT[n][m]  (float4 stores, conflict-free)
#pragma unroll
    for (int p = 0; p < 4; p++) {
        int nb = (p < 2) ? (tn * 4 + 2 * p) : (64 + tn * 4 + 2 * (p - 2));
#pragma unroll
        for (int c = 0; c < 2; c++) {
            int n = nb + c;
            float4 w0, w1;
            w0.x = fast_sin(OMEGA * av[0][2 * p + c]);
            w0.y = fast_sin(OMEGA * av[1][2 * p + c]);
            w0.z = fast_sin(OMEGA * av[2][2 * p + c]);
            w0.w = fast_sin(OMEGA * av[3][2 * p + c]);
            w1.x = fast_sin(OMEGA * av[4][2 * p + c]);
            w1.y = fast_sin(OMEGA * av[5][2 * p + c]);
            w1.z = fast_sin(OMEGA * av[6][2 * p + c]);
            w1.w = fast_sin(OMEGA * av[7][2 * p + c]);
            ((float4*)(hT + n * MROW))[tm]      = w0;
            ((float4*)(hT + n * MROW))[32 + tm] = w1;
        }
    }
}

__global__ void __launch_bounds__(THREADS, 1)
ecnr_kernel(const float* __restrict__ x,
            const int* __restrict__ mlp_idx,
            const int* __restrict__ block_idx,
            const float* __restrict__ latent_table,
            const float* __restrict__ cent0, const int* __restrict__ lab0, const float* __restrict__ bias0,
            const float* __restrict__ cent1, const int* __restrict__ lab1, const float* __restrict__ bias1,
            const float* __restrict__ cent2, const int* __restrict__ lab2, const float* __restrict__ bias2,
            const float* __restrict__ cent3, const int* __restrict__ lab3, const float* __restrict__ bias3,
            float* __restrict__ out) {
    extern __shared__ float sm[];
    float* hT = sm;                 // [128][256]
    float* Ws = sm + HT_SZ;         // [128][128]
    float* cs0 = sm + HT_SZ + WS_SZ;
    float* cs1 = cs0 + 256;
    float* cs2 = cs1 + 256;
    float* cs3 = cs2 + 256;
    float* bias_s = cs3 + 256;      // 128

    int tid = threadIdx.x;
    int b   = blockIdx.y;
    int pt0 = blockIdx.x * MROW;
    int mlp = mlp_idx[b];
    int blk = block_idx[b];

    // centroid tables (all 4 layers), layer-0 bias
    if (tid < 256) {
        cs0[tid] = cent0[tid];
        cs1[tid] = cent1[tid];
        cs2[tid] = cent2[tid];
        cs3[tid] = cent3[tid];
    }
    if (tid < HID) bias_s[tid] = bias0[mlp * HID + tid];

    // layer-0 input: rows 0..2 coords, rows 3..15 latent broadcast
    if (tid < MROW) {
        const float* xp = x + ((long)b * NPTS + pt0 + tid) * 3;
        hT[0 * MROW + tid] = xp[0];
        hT[1 * MROW + tid] = xp[1];
        hT[2 * MROW + tid] = xp[2];
    }
    const float* zrow = latent_table + ((long)mlp * 8 + blk) * 13;
    for (int i = tid; i < 13 * MROW; i += THREADS) {
        int r = i >> 8;       // / MROW
        int m = i & (MROW - 1);
        hT[(3 + r) * MROW + m] = zrow[r];
    }

    // *** cs0 must be fully written before dequant gathers from it ***
    __syncthreads();

    dequant(Ws, lab0 + mlp * (16 * HID), cs0, (16 * HID) / 4, tid);
    __syncthreads();

    int tm = tid & 31;
    int tn = tid >> 5;

    layer_gemm_sin<16>(hT, Ws, bias_s, tm, tn);
    dequant(Ws, lab1 + (long)mlp * (HID * HID), cs1, (HID * HID) / 4, tid);
    if (tid < HID) bias_s[tid] = bias1[mlp * HID + tid];
    __syncthreads();

    layer_gemm_sin<128>(hT, Ws, bias_s, tm, tn);
    dequant(Ws, lab2 + (long)mlp * (HID * HID), cs2, (HID * HID) / 4, tid);
    if (tid < HID) bias_s[tid] = bias2[mlp * HID + tid];
    __syncthreads();

    layer_gemm_sin<128>(hT, Ws, bias_s, tm, tn);
    // layer-3 weights (128x1) + bias
    if (tid < 32) {
        int4 v = ((const int4*)(lab3 + mlp * HID))[tid];
        float4 w;
        w.x = cs3[v.x]; w.y = cs3[v.y]; w.z = cs3[v.z]; w.w = cs3[v.w];
        ((float4*)Ws)[tid] = w;
    }
    if (tid == 0) bias_s[0] = bias3[mlp];
    __syncthreads();

    if (tid < MROW) {
        float s = 0.0f;
#pragma unroll 16
        for (int k = 0; k < HID; k++)
            s = fmaf(hT[k * MROW + tid], Ws[k], s);
        out[(long)b * NPTS + pt0 + tid] = s + bias_s[0];
    }
}

extern "C" void kernel_launch(void* const* d_in, const int* in_sizes, int n_in,
                              void* d_out, int out_size) {
    (void)n_in; (void)out_size;
    cudaFuncSetAttribute(ecnr_kernel,
                         cudaFuncAttributeMaxDynamicSharedMemorySize, SMEM_BYTES);
    int B = in_sizes[1];                 // number of samples (mlp_idx count)
    dim3 grid(NCHUNK, B);
    ecnr_kernel<<<grid, THREADS, SMEM_BYTES>>>(
        (const float*)d_in[0], (const int*)d_in[1], (const int*)d_in[2],
        (const float*)d_in[3],
        (const float*)d_in[4],  (const int*)d_in[5],  (const float*)d_in[6],
        (const float*)d_in[7],  (const int*)d_in[8],  (const float*)d_in[9],
        (const float*)d_in[10], (const int*)d_in[11], (const float*)d_in[12],
        (const float*)d_in[13], (const int*)d_in[14], (const float*)d_in[15],
        (float*)d_out);
}

// round 5
// speedup vs baseline: 1.0049x; 1.0049x over previous
#include <cuda_runtime.h>
#include <cstdint>

#define OMEGA 30.0f
#define HID 128
#define MROW 256          // points per CTA
#define THREADS 512
#define NPTS 2048
#define NCHUNK (NPTS / MROW)

// shared memory layout (in floats)
#define HT_SZ   (HID * MROW)          // 32768
#define WS_SZ   (HID * HID)           // 16384
#define SMEM_FLOATS (HT_SZ + WS_SZ + 4*256 + 128)
#define SMEM_BYTES  (SMEM_FLOATS * 4)

// ---------------- packed f32x2 helpers ----------------
__device__ __forceinline__ uint64_t pack2(float lo, float hi) {
    uint64_t r;
    asm("mov.b64 %0, {%1, %2};" : "=l"(r) : "f"(lo), "f"(hi));
    return r;
}
__device__ __forceinline__ float2 unpack2(uint64_t v) {
    float2 f;
    asm("mov.b64 {%0, %1}, %2;" : "=f"(f.x), "=f"(f.y) : "l"(v));
    return f;
}
__device__ __forceinline__ uint64_t fma2(uint64_t a, uint64_t b, uint64_t c) {
    uint64_t d;
    asm("fma.rn.f32x2 %0, %1, %2, %3;" : "=l"(d) : "l"(a), "l"(b), "l"(c));
    return d;
}

// ---------------- accurate fast sin ----------------
// |x| < ~600 here. Reduce by pi (2-term Cody-Waite), deg-11 odd minimax poly
// (valid on [-pi/2,pi/2] after rintf reduction), sign flip by parity of k.
// Abs err ~1e-7.
__device__ __forceinline__ float fast_sin(float x) {
    float k = rintf(x * 0.3183098861837907f);
    float r = fmaf(k, -3.14159274f, x);
    r = fmaf(k, 8.742277657e-8f, r);
    float y = r * r;
    float p = fmaf(y, -2.3889859e-8f, 2.7525562e-6f);
    p = fmaf(y, p, -1.9840874e-4f);
    p = fmaf(y, p, 8.3333310e-3f);
    p = fmaf(y, p, -1.6666667e-1f);
    p = fmaf(y, p, 1.0f);
    p = r * p;
    int ki = (int)k;
    return __int_as_float(__float_as_int(p) ^ ((ki & 1) << 31));
}

// ---------------- codebook dequant into smem ----------------
__device__ __forceinline__ void dequant(float* Ws, const int* labels,
                                        const float* cent, int n4, int tid) {
    const int4* lb = (const int4*)labels;
    float4* w4 = (float4*)Ws;
    for (int i = tid; i < n4; i += THREADS) {
        int4 v = lb[i];
        float4 w;
        w.x = cent[v.x]; w.y = cent[v.y]; w.z = cent[v.z]; w.w = cent[v.w];
        w4[i] = w;
    }
}

// ---------------- one hidden layer: hT(new) = sin(OMEGA*(hT @ Ws + bias)) ----
// hT: [K rows][MROW pts], Ws: [K rows][HID cols]. Thread tile 8 pts x 8 outs.
// Contains ONE internal __syncthreads between reads (gemm+bias) and writes.
template<int K>
__device__ __forceinline__ void layer_gemm_sin(float* hT, const float* Ws,
                                               const float* bias_s,
                                               int tm, int tn) {
    uint64_t acc[8][4];
#pragma unroll
    for (int i = 0; i < 8; i++)
#pragma unroll
        for (int j = 0; j < 4; j++) acc[i][j] = 0ULL;

    const float4* hp = (const float4*)hT;
    const float4* wp = (const float4*)Ws;
#pragma unroll 8
    for (int k = 0; k < K; k++) {
        float4 A0 = hp[k * (MROW / 4) + tm];
        float4 A1 = hp[k * (MROW / 4) + 32 + tm];
        float4 B0 = wp[k * (HID / 4) + tn];
        float4 B1 = wp[k * (HID / 4) + 16 + tn];
        uint64_t b0 = pack2(B0.x, B0.y);
        uint64_t b1 = pack2(B0.z, B0.w);
        uint64_t b2 = pack2(B1.x, B1.y);
        uint64_t b3 = pack2(B1.z, B1.w);
        float am[8] = {A0.x, A0.y, A0.z, A0.w, A1.x, A1.y, A1.z, A1.w};
#pragma unroll
        for (int mi = 0; mi < 8; mi++) {
            uint64_t a2 = pack2(am[mi], am[mi]);
            acc[mi][0] = fma2(a2, b0, acc[mi][0]);
            acc[mi][1] = fma2(a2, b1, acc[mi][1]);
            acc[mi][2] = fma2(a2, b2, acc[mi][2]);
            acc[mi][3] = fma2(a2, b3, acc[mi][3]);
        }
    }

    // bias add (reads bias_s BEFORE the sync so caller may overwrite it after)
    float av[8][8];
#pragma unroll
    for (int p = 0; p < 4; p++) {
        int nb = (p < 2) ? (tn * 4 + 2 * p) : (64 + tn * 4 + 2 * (p - 2));
        float bx = bias_s[nb];
        float by = bias_s[nb + 1];
#pragma unroll
        for (int mi = 0; mi < 8; mi++) {
            float2 v = unpack2(acc[mi][p]);
            av[mi][2 * p]     = v.x + bx;
            av[mi][2 * p + 1] = v.y + by;
        }
    }
    __syncthreads();   // all reads of hT/Ws/bias_s complete

    // sin + writeback into hT[n][m]  (float4 stores, conflict-free)
#pragma unroll
    for (int p = 0; p < 4; p++) {
        int nb = (p < 2) ? (tn * 4 + 2 * p) : (64 + tn * 4 + 2 * (p - 2));
#pragma unroll
        for (int c = 0; c < 2; c++) {
            int n = nb + c;
            float4 w0, w1;
            w0.x = fast_sin(OMEGA * av[0][2 * p + c]);
            w0.y = fast_sin(OMEGA * av[1][2 * p + c]);
            w0.z = fast_sin(OMEGA * av[2][2 * p + c]);
            w0.w = fast_sin(OMEGA * av[3][2 * p + c]);
            w1.x = fast_sin(OMEGA * av[4][2 * p + c]);
            w1.y = fast_sin(OMEGA * av[5][2 * p + c]);
            w1.z = fast_sin(OMEGA * av[6][2 * p + c]);
            w1.w = fast_sin(OMEGA * av[7][2 * p + c]);
            ((float4*)(hT + n * MROW))[tm]      = w0;
            ((float4*)(hT + n * MROW))[32 + tm] = w1;
        }
    }
}

__global__ void __launch_bounds__(THREADS, 1)
ecnr_kernel(const float* __restrict__ x,
            const int* __restrict__ mlp_idx,
            const int* __restrict__ block_idx,
            const float* __restrict__ latent_table,
            const float* __restrict__ cent0, const int* __restrict__ lab0, const float* __restrict__ bias0,
            const float* __restrict__ cent1, const int* __restrict__ lab1, const float* __restrict__ bias1,
            const float* __restrict__ cent2, const int* __restrict__ lab2, const float* __restrict__ bias2,
            const float* __restrict__ cent3, const int* __restrict__ lab3, const float* __restrict__ bias3,
            float* __restrict__ out) {
    extern __shared__ float sm[];
    float* hT = sm;                 // [128][256]
    float* Ws = sm + HT_SZ;         // [128][128]
    float* cs0 = sm + HT_SZ + WS_SZ;
    float* cs1 = cs0 + 256;
    float* cs2 = cs1 + 256;
    float* cs3 = cs2 + 256;
    float* bias_s = cs3 + 256;      // 128

    int tid = threadIdx.x;
    int b   = blockIdx.y;
    int pt0 = blockIdx.x * MROW;
    int mlp = mlp_idx[b];
    int blk = block_idx[b];

    // centroid tables (all 4 layers), layer-0 bias
    if (tid < 256) {
        cs0[tid] = cent0[tid];
        cs1[tid] = cent1[tid];
        cs2[tid] = cent2[tid];
        cs3[tid] = cent3[tid];
    }
    if (tid < HID) bias_s[tid] = bias0[mlp * HID + tid];

    // layer-0 input: rows 0..2 coords, rows 3..15 latent broadcast
    if (tid < MROW) {
        const float* xp = x + ((long)b * NPTS + pt0 + tid) * 3;
        hT[0 * MROW + tid] = xp[0];
        hT[1 * MROW + tid] = xp[1];
        hT[2 * MROW + tid] = xp[2];
    }
    const float* zrow = latent_table + ((long)mlp * 8 + blk) * 13;
    for (int i = tid; i < 13 * MROW; i += THREADS) {
        int r = i >> 8;       // / MROW
        int m = i & (MROW - 1);
        hT[(3 + r) * MROW + m] = zrow[r];
    }

    // *** cs0 must be fully written before dequant gathers from it ***
    __syncthreads();

    dequant(Ws, lab0 + mlp * (16 * HID), cs0, (16 * HID) / 4, tid);
    __syncthreads();

    int tm = tid & 31;
    int tn = tid >> 5;

    layer_gemm_sin<16>(hT, Ws, bias_s, tm, tn);
    dequant(Ws, lab1 + (long)mlp * (HID * HID), cs1, (HID * HID) / 4, tid);
    if (tid < HID) bias_s[tid] = bias1[mlp * HID + tid];
    __syncthreads();

    layer_gemm_sin<128>(hT, Ws, bias_s, tm, tn);
    dequant(Ws, lab2 + (long)mlp * (HID * HID), cs2, (HID * HID) / 4, tid);
    if (tid < HID) bias_s[tid] = bias2[mlp * HID + tid];
    __syncthreads();

    layer_gemm_sin<128>(hT, Ws, bias_s, tm, tn);
    // layer-3 weights (128x1) + bias
    if (tid < 32) {
        int4 v = ((const int4*)(lab3 + mlp * HID))[tid];
        float4 w;
        w.x = cs3[v.x]; w.y = cs3[v.y]; w.z = cs3[v.z]; w.w = cs3[v.w];
        ((float4*)Ws)[tid] = w;
    }
    if (tid == 0) bias_s[0] = bias3[mlp];
    __syncthreads();

    if (tid < MROW) {
        float s = 0.0f;
#pragma unroll 16
        for (int k = 0; k < HID; k++)
            s = fmaf(hT[k * MROW + tid], Ws[k], s);
        out[(long)b * NPTS + pt0 + tid] = s + bias_s[0];
    }
}

extern "C" void kernel_launch(void* const* d_in, const int* in_sizes, int n_in,
                              void* d_out, int out_size) {
    (void)n_in; (void)out_size;
    cudaFuncSetAttribute(ecnr_kernel,
                         cudaFuncAttributeMaxDynamicSharedMemorySize, SMEM_BYTES);
    int B = in_sizes[1];                 // number of samples (mlp_idx count)
    dim3 grid(NCHUNK, B);
    ecnr_kernel<<<grid, THREADS, SMEM_BYTES>>>(
        (const float*)d_in[0], (const int*)d_in[1], (const int*)d_in[2],
        (const float*)d_in[3],
        (const float*)d_in[4],  (const int*)d_in[5],  (const float*)d_in[6],
        (const float*)d_in[7],  (const int*)d_in[8],  (const float*)d_in[9],
        (const float*)d_in[10], (const int*)d_in[11], (const float*)d_in[12],
        (const float*)d_in[13], (const int*)d_in[14], (const float*)d_in[15],
        (float*)d_out);
}

// round 9
// speedup vs baseline: 1.0422x; 1.0371x over previous
#include <cuda_runtime.h>
#include <cstdint>

#define OMEGA 30.0f
#define HID 128
#define MROW 256          // points per CTA
#define THREADS 512
#define NPTS 2048
#define NCHUNK (NPTS / MROW)

// shared memory layout (in floats)
#define HT_SZ   (HID * MROW)          // 32768 floats (128KB)
#define WS_SZ   (HID * HID)           // 16384 floats (64KB)
#define SMEM_FLOATS (HT_SZ + WS_SZ + 4*256 + 128 + 512 + 16)
#define SMEM_BYTES  (SMEM_FLOATS * 4)

// ---------------- packed f32x2 helpers ----------------
__device__ __forceinline__ uint64_t pack2(float lo, float hi) {
    uint64_t r;
    asm("mov.b64 %0, {%1, %2};" : "=l"(r) : "f"(lo), "f"(hi));
    return r;
}
__device__ __forceinline__ uint64_t fma2(uint64_t a, uint64_t b, uint64_t c) {
    uint64_t d;
    asm("fma.rn.f32x2 %0, %1, %2, %3;" : "=l"(d) : "l"(a), "l"(b), "l"(c));
    return d;
}
__device__ __forceinline__ uint64_t add2(uint64_t a, uint64_t b) {
    uint64_t d;
    asm("add.rn.f32x2 %0, %1, %2;" : "=l"(d) : "l"(a), "l"(b));
    return d;
}
__device__ __forceinline__ uint64_t mul2(uint64_t a, uint64_t b) {
    uint64_t d;
    asm("mul.rn.f32x2 %0, %1, %2;" : "=l"(d) : "l"(a), "l"(b));
    return d;
}
#define DUP(c) pack2((c), (c))

// ---------------- packed sin: sin(x) for both lanes, |x| < ~1e5 -------------
// k = rint(x/pi) via magic-constant add (parity from low mantissa bit),
// r = x - k*pi (2-term Cody-Waite), deg-11 odd minimax poly, sign = parity.
// Abs err ~1e-7 per lane.
__device__ __forceinline__ uint64_t sin2(uint64_t x2) {
    uint64_t y2 = fma2(x2, DUP(0.3183098861837907f), DUP(12582912.0f));
    uint64_t sgn = (y2 & 0x0000000100000001ULL) << 31;
    uint64_t k2 = add2(y2, DUP(-12582912.0f));
    uint64_t r2 = fma2(k2, DUP(-3.14159274f), x2);
    r2 = fma2(k2, DUP(8.742277657e-8f), r2);
    uint64_t yy = mul2(r2, r2);
    uint64_t p = fma2(yy, DUP(-2.3889859e-8f), DUP(2.7525562e-6f));
    p = fma2(yy, p, DUP(-1.9840874e-4f));
    p = fma2(yy, p, DUP(8.3333310e-3f));
    p = fma2(yy, p, DUP(-1.6666667e-1f));
    p = fma2(yy, p, DUP(1.0f));
    p = mul2(r2, p);
    return p ^ sgn;
}

// ---------------- codebook dequant into smem ----------------
__device__ __forceinline__ void dequant(float* Ws, const int* labels,
                                        const float* cent, int n4, int tid) {
    const int4* lb = (const int4*)labels;
    float4* w4 = (float4*)Ws;
    for (int i = tid; i < n4; i += THREADS) {
        int4 v = lb[i];
        float4 w;
        w.x = cent[v.x]; w.y = cent[v.y]; w.z = cent[v.z]; w.w = cent[v.w];
        w4[i] = w;
    }
}

// ---------------- one hidden layer: hT(new) = sin(OMEGA*hT@Ws + biasO) ------
// hT: [K rows][MROW pts], Ws: [K rows][HID cols]. biasO holds OMEGA*bias.
// Warp grid 4x4: wr = wid&3 (points), wc = wid>>2 (cols).
// Thread: pts {q0..q0+3} U {q0+128..q0+131} (as f32x2 pairs), cols col0..col0+7.
// ONE internal __syncthreads between reads (gemm+bias) and writes.
template<int K>
__device__ __forceinline__ void layer_gemm_sin(float* hT, const float* Ws,
                                               const float* biasO,
                                               int q0, int col0) {
    uint64_t acc[4][8];
#pragma unroll
    for (int p = 0; p < 4; p++)
#pragma unroll
        for (int c = 0; c < 8; c++) acc[p][c] = 0ULL;

#pragma unroll 4
    for (int k = 0; k < K; k++) {
        const float* arow = hT + k * MROW;
        ulonglong2 A0 = *(const ulonglong2*)(arow + q0);        // pts q0..q0+3
        ulonglong2 A1 = *(const ulonglong2*)(arow + q0 + 128);  // pts +128
        uint64_t A[4] = {A0.x, A0.y, A1.x, A1.y};
        const float* brow = Ws + k * HID + col0;
        float4 b0 = *(const float4*)brow;
        float4 b1 = *(const float4*)(brow + 4);
        float bs[8] = {b0.x, b0.y, b0.z, b0.w, b1.x, b1.y, b1.z, b1.w};
#pragma unroll
        for (int c = 0; c < 8; c++) {
            uint64_t bw = pack2(bs[c], bs[c]);
            acc[0][c] = fma2(A[0], bw, acc[0][c]);
            acc[1][c] = fma2(A[1], bw, acc[1][c]);
            acc[2][c] = fma2(A[2], bw, acc[2][c]);
            acc[3][c] = fma2(A[3], bw, acc[3][c]);
        }
    }

    // epilogue: x = OMEGA*acc + biasO (biasO pre-scaled), packed sin — all in
    // registers; bias read BEFORE the sync so caller may overwrite after.
    const uint64_t om2 = DUP(OMEGA);
#pragma unroll
    for (int c = 0; c < 8; c++) {
        uint64_t bw = DUP(biasO[col0 + c]);
#pragma unroll
        for (int p = 0; p < 4; p++)
            acc[p][c] = sin2(fma2(acc[p][c], om2, bw));
    }
    __syncthreads();   // all reads of hT/Ws/biasO complete

    // writeback: packed pairs are consecutive points of one column
#pragma unroll
    for (int c = 0; c < 8; c++) {
        float* dst = hT + (col0 + c) * MROW;
        *(ulonglong2*)(dst + q0)       = make_ulonglong2(acc[0][c], acc[1][c]);
        *(ulonglong2*)(dst + q0 + 128) = make_ulonglong2(acc[2][c], acc[3][c]);
    }
}

__global__ void __launch_bounds__(THREADS, 1)
ecnr_kernel(const float* __restrict__ x,
            const int* __restrict__ mlp_idx,
            const int* __restrict__ block_idx,
            const float* __restrict__ latent_table,
            const float* __restrict__ cent0, const int* __restrict__ lab0, const float* __restrict__ bias0,
            const float* __restrict__ cent1, const int* __restrict__ lab1, const float* __restrict__ bias1,
            const float* __restrict__ cent2, const int* __restrict__ lab2, const float* __restrict__ bias2,
            const float* __restrict__ cent3, const int* __restrict__ lab3, const float* __restrict__ bias3,
            float* __restrict__ out) {
    extern __shared__ float sm[];
    float* hT = sm;                 // [128][256]
    float* Ws = sm + HT_SZ;         // [128][128]
    float* cs0 = sm + HT_SZ + WS_SZ;
    float* cs1 = cs0 + 256;
    float* cs2 = cs1 + 256;
    float* cs3 = cs2 + 256;
    float* bias_s = cs3 + 256;      // 128 (holds OMEGA*bias for layers 0-2)
    float* part   = bias_s + 128;   // 512
    float* b3s    = part + 512;     // 1

    int tid = threadIdx.x;
    int b   = blockIdx.y;
    int pt0 = blockIdx.x * MROW;
    int mlp = mlp_idx[b];
    int blk = block_idx[b];

    // centroid tables (all 4 layers), layer-0 bias (pre-scaled by OMEGA)
    if (tid < 256) {
        cs0[tid] = cent0[tid];
        cs1[tid] = cent1[tid];
        cs2[tid] = cent2[tid];
        cs3[tid] = cent3[tid];
    }
    if (tid < HID) bias_s[tid] = OMEGA * bias0[mlp * HID + tid];
    if (tid == 0)  b3s[0] = bias3[mlp];

    // layer-0 input: rows 0..2 coords, rows 3..15 latent broadcast
    if (tid < MROW) {
        const float* xp = x + ((long)b * NPTS + pt0 + tid) * 3;
        hT[0 * MROW + tid] = xp[0];
        hT[1 * MROW + tid] = xp[1];
        hT[2 * MROW + tid] = xp[2];
    }
    const float* zrow = latent_table + ((long)mlp * 8 + blk) * 13;
    for (int i = tid; i < 13 * MROW; i += THREADS) {
        int r = i >> 8;       // / MROW
        int m = i & (MROW - 1);
        hT[(3 + r) * MROW + m] = zrow[r];
    }

    // cs0 must be fully written before dequant gathers from it
    __syncthreads();

    dequant(Ws, lab0 + mlp * (16 * HID), cs0, (16 * HID) / 4, tid);
    __syncthreads();

    // 2D tiling indices
    int wid = tid >> 5, lane = tid & 31;
    int lr = lane & 7, lc = lane >> 3;
    int wr = wid & 3, wc = wid >> 2;
    int q0   = wr * 32 + lr * 4;       // point base (pairs q0..q0+3, +128)
    int col0 = wc * 32 + lc * 8;       // 8 columns

    layer_gemm_sin<16>(hT, Ws, bias_s, q0, col0);
    dequant(Ws, lab1 + (long)mlp * (HID * HID), cs1, (HID * HID) / 4, tid);
    if (tid < HID) bias_s[tid] = OMEGA * bias1[mlp * HID + tid];
    __syncthreads();

    layer_gemm_sin<128>(hT, Ws, bias_s, q0, col0);
    dequant(Ws, lab2 + (long)mlp * (HID * HID), cs2, (HID * HID) / 4, tid);
    if (tid < HID) bias_s[tid] = OMEGA * bias2[mlp * HID + tid];
    __syncthreads();

    layer_gemm_sin<128>(hT, Ws, bias_s, q0, col0);
    // layer-3 weights (128x1) + bias
    if (tid < 32) {
        int4 v = ((const int4*)(lab3 + mlp * HID))[tid];
        float4 w;
        w.x = cs3[v.x]; w.y = cs3[v.y]; w.z = cs3[v.z]; w.w = cs3[v.w];
        ((float4*)Ws)[tid] = w;
    }
    __syncthreads();

    // layer 3: dot over 128 dims, split over 2 halves of k
    {
        int pt = tid & 255, half = tid >> 8;
        float s = 0.0f;
        const float* hp = hT + half * 64 * MROW + pt;
        const float* wp = Ws + half * 64;
#pragma unroll 16
        for (int k = 0; k < 64; k++)
            s = fmaf(hp[k * MROW], wp[k], s);
        part[half * 256 + pt] = s;
    }
    __syncthreads();
    if (tid < MROW) {
        out[(long)b * NPTS + pt0 + tid] = part[tid] + part[256 + tid] + b3s[0];
    }
}

extern "C" void kernel_launch(void* const* d_in, const int* in_sizes, int n_in,
                              void* d_out, int out_size) {
    (void)n_in; (void)out_size;
    cudaFuncSetAttribute(ecnr_kernel,
                         cudaFuncAttributeMaxDynamicSharedMemorySize, SMEM_BYTES);
    int B = in_sizes[1];                 // number of samples (mlp_idx count)
    dim3 grid(NCHUNK, B);
    ecnr_kernel<<<grid, THREADS, SMEM_BYTES>>>(
        (const float*)d_in[0], (const int*)d_in[1], (const int*)d_in[2],
        (const float*)d_in[3],
        (const float*)d_in[4],  (const int*)d_in[5],  (const float*)d_in[6],
        (const float*)d_in[7],  (const int*)d_in[8],  (const float*)d_in[9],
        (const float*)d_in[10], (const int*)d_in[11], (const float*)d_in[12],
        (const float*)d_in[13], (const int*)d_in[14], (const float*)d_in[15],
        (float*)d_out);
}

// round 10
// speedup vs baseline: 1.0805x; 1.0367x over previous
#include <cuda_runtime.h>
#include <cstdint>

#define OMEGA 30.0f
#define HID 128
#define MROW 256          // points per CTA
#define THREADS 512
#define NPTS 2048
#define NCHUNK (NPTS / MROW)

// shared memory layout (in floats)
#define HT_SZ   (HID * MROW)          // 32768 floats (128KB)
#define WS_SZ   (HID * HID)           // 16384 floats (64KB)
#define SMEM_FLOATS (HT_SZ + WS_SZ + 4*256 + 128 + 512 + 16)
#define SMEM_BYTES  (SMEM_FLOATS * 4)

// ---------------- packed f32x2 helpers ----------------
__device__ __forceinline__ uint64_t pack2(float lo, float hi) {
    uint64_t r;
    asm("mov.b64 %0, {%1, %2};" : "=l"(r) : "f"(lo), "f"(hi));
    return r;
}
__device__ __forceinline__ uint64_t fma2(uint64_t a, uint64_t b, uint64_t c) {
    uint64_t d;
    asm("fma.rn.f32x2 %0, %1, %2, %3;" : "=l"(d) : "l"(a), "l"(b), "l"(c));
    return d;
}
__device__ __forceinline__ uint64_t add2(uint64_t a, uint64_t b) {
    uint64_t d;
    asm("add.rn.f32x2 %0, %1, %2;" : "=l"(d) : "l"(a), "l"(b));
    return d;
}
__device__ __forceinline__ uint64_t mul2(uint64_t a, uint64_t b) {
    uint64_t d;
    asm("mul.rn.f32x2 %0, %1, %2;" : "=l"(d) : "l"(a), "l"(b));
    return d;
}
#define DUP(c) pack2((c), (c))

// ---------------- packed sin: sin(x) for both lanes, |x| < ~1e5 -------------
__device__ __forceinline__ uint64_t sin2(uint64_t x2) {
    uint64_t y2 = fma2(x2, DUP(0.3183098861837907f), DUP(12582912.0f));
    uint64_t sgn = (y2 & 0x0000000100000001ULL) << 31;
    uint64_t k2 = add2(y2, DUP(-12582912.0f));
    uint64_t r2 = fma2(k2, DUP(-3.14159274f), x2);
    r2 = fma2(k2, DUP(8.742277657e-8f), r2);
    uint64_t yy = mul2(r2, r2);
    uint64_t p = fma2(yy, DUP(-2.3889859e-8f), DUP(2.7525562e-6f));
    p = fma2(yy, p, DUP(-1.9840874e-4f));
    p = fma2(yy, p, DUP(8.3333310e-3f));
    p = fma2(yy, p, DUP(-1.6666667e-1f));
    p = fma2(yy, p, DUP(1.0f));
    p = mul2(r2, p);
    return p ^ sgn;
}

// ---------------- one hidden layer: hT(new) = sin(OMEGA*hT@Ws + biasO) ------
// hT: [K rows][MROW pts], Ws: [K rows][HID cols]. biasO holds OMEGA*bias.
// Thread tile: pts {q0..q0+3, q0+128..+131} (f32x2 pairs) x cols col0..col0+7.
// PF=1: after the internal sync, prefetch+dequant the NEXT layer's weights
// (4096 int4 labels) and bias into Ws/bias_slot, overlapped with writeback.
// Caller must __syncthreads() after return before using Ws/bias_slot.
template<int K, int PF>
__device__ __forceinline__ void layer_gemm_sin(float* hT, float* Ws,
                                               const float* biasO,
                                               int q0, int col0,
                                               const int4* nlab4,
                                               const float* ncent,
                                               const float* nbias,
                                               float* bias_slot, int tid) {
    uint64_t acc[4][8];
#pragma unroll
    for (int p = 0; p < 4; p++)
#pragma unroll
        for (int c = 0; c < 8; c++) acc[p][c] = 0ULL;

#pragma unroll 4
    for (int k = 0; k < K; k++) {
        const float* arow = hT + k * MROW;
        ulonglong2 A0 = *(const ulonglong2*)(arow + q0);        // pts q0..q0+3
        ulonglong2 A1 = *(const ulonglong2*)(arow + q0 + 128);  // pts +128
        uint64_t A[4] = {A0.x, A0.y, A1.x, A1.y};
        const float* brow = Ws + k * HID + col0;
        float4 b0 = *(const float4*)brow;
        float4 b1 = *(const float4*)(brow + 4);
        float bs[8] = {b0.x, b0.y, b0.z, b0.w, b1.x, b1.y, b1.z, b1.w};
#pragma unroll
        for (int c = 0; c < 8; c++) {
            uint64_t bw = pack2(bs[c], bs[c]);
            acc[0][c] = fma2(A[0], bw, acc[0][c]);
            acc[1][c] = fma2(A[1], bw, acc[1][c]);
            acc[2][c] = fma2(A[2], bw, acc[2][c]);
            acc[3][c] = fma2(A[3], bw, acc[3][c]);
        }
    }

    // epilogue: x = OMEGA*acc + biasO (pre-scaled), packed sin (registers only)
    const uint64_t om2 = DUP(OMEGA);
#pragma unroll
    for (int c = 0; c < 8; c++) {
        uint64_t bw = DUP(biasO[col0 + c]);
#pragma unroll
        for (int p = 0; p < 4; p++)
            acc[p][c] = sin2(fma2(acc[p][c], om2, bw));
    }
    __syncthreads();   // all reads of hT/Ws/biasO complete

    // ---- next-layer prefetch: issue label LDGs early (latency hides behind
    // the sin writeback below), gather+store after.
    int4 v[4];
    float nb = 0.0f;
    if (PF) {
#pragma unroll
        for (int j = 0; j < 4; j++) v[j] = nlab4[tid + j * 512];
        if (tid < HID) nb = nbias[tid];
    }

    // writeback first half (cols 0..3)
#pragma unroll
    for (int c = 0; c < 4; c++) {
        float* dst = hT + (col0 + c) * MROW;
        *(ulonglong2*)(dst + q0)       = make_ulonglong2(acc[0][c], acc[1][c]);
        *(ulonglong2*)(dst + q0 + 128) = make_ulonglong2(acc[2][c], acc[3][c]);
    }

    int4 v2[4];
    if (PF) {
#pragma unroll
        for (int j = 0; j < 4; j++) v2[j] = nlab4[tid + (4 + j) * 512];
    }

    // writeback second half (cols 4..7)
#pragma unroll
    for (int c = 4; c < 8; c++) {
        float* dst = hT + (col0 + c) * MROW;
        *(ulonglong2*)(dst + q0)       = make_ulonglong2(acc[0][c], acc[1][c]);
        *(ulonglong2*)(dst + q0 + 128) = make_ulonglong2(acc[2][c], acc[3][c]);
    }

    if (PF) {
        float4* w4 = (float4*)Ws;
#pragma unroll
        for (int j = 0; j < 4; j++) {
            int4 u = v[j];
            float4 w;
            w.x = ncent[u.x]; w.y = ncent[u.y]; w.z = ncent[u.z]; w.w = ncent[u.w];
            w4[tid + j * 512] = w;
        }
#pragma unroll
        for (int j = 0; j < 4; j++) {
            int4 u = v2[j];
            float4 w;
            w.x = ncent[u.x]; w.y = ncent[u.y]; w.z = ncent[u.z]; w.w = ncent[u.w];
            w4[tid + (4 + j) * 512] = w;
        }
        if (tid < HID) bias_slot[tid] = OMEGA * nb;
    }
}

__global__ void __launch_bounds__(THREADS, 1)
ecnr_kernel(const float* __restrict__ x,
            const int* __restrict__ mlp_idx,
            const int* __restrict__ block_idx,
            const float* __restrict__ latent_table,
            const float* __restrict__ cent0, const int* __restrict__ lab0, const float* __restrict__ bias0,
            const float* __restrict__ cent1, const int* __restrict__ lab1, const float* __restrict__ bias1,
            const float* __restrict__ cent2, const int* __restrict__ lab2, const float* __restrict__ bias2,
            const float* __restrict__ cent3, const int* __restrict__ lab3, const float* __restrict__ bias3,
            float* __restrict__ out) {
    extern __shared__ float sm[];
    float* hT = sm;                 // [128][256]
    float* Ws = sm + HT_SZ;         // [128][128]
    float* cs0 = sm + HT_SZ + WS_SZ;
    float* cs1 = cs0 + 256;
    float* cs2 = cs1 + 256;
    float* cs3 = cs2 + 256;
    float* bias_s = cs3 + 256;      // 128 (holds OMEGA*bias for layers 0-2)
    float* part   = bias_s + 128;   // 512
    float* b3s    = part + 512;     // 1

    int tid = threadIdx.x;
    int b   = blockIdx.y;
    int pt0 = blockIdx.x * MROW;
    int mlp = mlp_idx[b];
    int blk = block_idx[b];

    // centroid tables (all 4 layers), layer-0 bias (pre-scaled by OMEGA)
    if (tid < 256) {
        cs0[tid] = cent0[tid];
        cs1[tid] = cent1[tid];
        cs2[tid] = cent2[tid];
        cs3[tid] = cent3[tid];
    }
    if (tid < HID) bias_s[tid] = OMEGA * bias0[mlp * HID + tid];
    if (tid == 0)  b3s[0] = bias3[mlp];

    // layer-0 input: rows 0..2 coords, rows 3..15 latent broadcast
    if (tid < MROW) {
        const float* xp = x + ((long)b * NPTS + pt0 + tid) * 3;
        hT[0 * MROW + tid] = xp[0];
        hT[1 * MROW + tid] = xp[1];
        hT[2 * MROW + tid] = xp[2];
    }
    const float* zrow = latent_table + ((long)mlp * 8 + blk) * 13;
    for (int i = tid; i < 13 * MROW; i += THREADS) {
        int r = i >> 8;       // / MROW
        int m = i & (MROW - 1);
        hT[(3 + r) * MROW + m] = zrow[r];
    }

    // layer-0 dequant (512 int4 -> one per thread); cs0 written above
    int4 v0 = ((const int4*)(lab0 + mlp * (16 * HID)))[tid];
    __syncthreads();            // cs0 visible (and hT writes done)
    {
        float4 w;
        w.x = cs0[v0.x]; w.y = cs0[v0.y]; w.z = cs0[v0.z]; w.w = cs0[v0.w];
        ((float4*)Ws)[tid] = w;
    }
    __syncthreads();

    // 2D tiling indices
    int wid = tid >> 5, lane = tid & 31;
    int lr = lane & 7, lc = lane >> 3;
    int wr = wid & 3, wc = wid >> 2;
    int q0   = wr * 32 + lr * 4;       // point base (pairs q0..q0+3, +128)
    int col0 = wc * 32 + lc * 8;       // 8 columns

    layer_gemm_sin<16, 1>(hT, Ws, bias_s, q0, col0,
                          (const int4*)(lab1 + (long)mlp * (HID * HID)),
                          cs1, bias1 + mlp * HID, bias_s, tid);
    __syncthreads();

    layer_gemm_sin<128, 1>(hT, Ws, bias_s, q0, col0,
                           (const int4*)(lab2 + (long)mlp * (HID * HID)),
                           cs2, bias2 + mlp * HID, bias_s, tid);
    __syncthreads();

    layer_gemm_sin<128, 0>(hT, Ws, bias_s, q0, col0,
                           nullptr, nullptr, nullptr, nullptr, tid);

    // layer-3 weights (128x1)
    if (tid < 32) {
        int4 v = ((const int4*)(lab3 + mlp * HID))[tid];
        float4 w;
        w.x = cs3[v.x]; w.y = cs3[v.y]; w.z = cs3[v.z]; w.w = cs3[v.w];
        ((float4*)Ws)[tid] = w;
    }
    __syncthreads();

    // layer 3: dot over 128 dims, split over 2 halves of k
    {
        int pt = tid & 255, half = tid >> 8;
        float s = 0.0f;
        const float* hp = hT + half * 64 * MROW + pt;
        const float* wp = Ws + half * 64;
#pragma unroll 16
        for (int k = 0; k < 64; k++)
            s = fmaf(hp[k * MROW], wp[k], s);
        part[half * 256 + pt] = s;
    }
    __syncthreads();
    if (tid < MROW) {
        out[(long)b * NPTS + pt0 + tid] = part[tid] + part[256 + tid] + b3s[0];
    }
}

extern "C" void kernel_launch(void* const* d_in, const int* in_sizes, int n_in,
                              void* d_out, int out_size) {
    (void)n_in; (void)out_size;
    cudaFuncSetAttribute(ecnr_kernel,
                         cudaFuncAttributeMaxDynamicSharedMemorySize, SMEM_BYTES);
    int B = in_sizes[1];                 // number of samples (mlp_idx count)
    dim3 grid(NCHUNK, B);
    ecnr_kernel<<<grid, THREADS, SMEM_BYTES>>>(
        (const float*)d_in[0], (const int*)d_in[1], (const int*)d_in[2],
        (const float*)d_in[3],
        (const float*)d_in[4],  (const int*)d_in[5],  (const float*)d_in[6],
        (const float*)d_in[7],  (const int*)d_in[8],  (const float*)d_in[9],
        (const float*)d_in[10], (const int*)d_in[11], (const float*)d_in[12],
        (const float*)d_in[13], (const int*)d_in[14], (const float*)d_in[15],
        (float*)d_out);
}

// round 11
// speedup vs baseline: 1.0934x; 1.0119x over previous
#include <cuda_runtime.h>
#include <cstdint>

#define OMEGA 30.0f
#define HID 128
#define MROW 256          // points per CTA
#define THREADS 512
#define NPTS 2048
#define NCHUNK (NPTS / MROW)

// shared memory layout (in floats)
#define HT_SZ   (HID * MROW)          // 32768 floats (128KB)
#define WS_SZ   (HID * HID)           // 16384 floats (64KB)
#define SMEM_FLOATS (HT_SZ + WS_SZ + 4*256 + 128 + 512 + 128 + 32)
#define SMEM_BYTES  (SMEM_FLOATS * 4)

// ---------------- packed f32x2 helpers ----------------
__device__ __forceinline__ uint64_t pack2(float lo, float hi) {
    uint64_t r;
    asm("mov.b64 %0, {%1, %2};" : "=l"(r) : "f"(lo), "f"(hi));
    return r;
}
// shared operand first (slot-0 reuse probe)
__device__ __forceinline__ uint64_t fma2(uint64_t a, uint64_t b, uint64_t c) {
    uint64_t d;
    asm("fma.rn.f32x2 %0, %1, %2, %3;" : "=l"(d) : "l"(a), "l"(b), "l"(c));
    return d;
}
__device__ __forceinline__ uint64_t add2(uint64_t a, uint64_t b) {
    uint64_t d;
    asm("add.rn.f32x2 %0, %1, %2;" : "=l"(d) : "l"(a), "l"(b));
    return d;
}
__device__ __forceinline__ uint64_t mul2(uint64_t a, uint64_t b) {
    uint64_t d;
    asm("mul.rn.f32x2 %0, %1, %2;" : "=l"(d) : "l"(a), "l"(b));
    return d;
}
#define DUP(c) pack2((c), (c))

// ---------------- packed sin: sin(x) for both lanes, |x| < ~1e5 -------------
__device__ __forceinline__ uint64_t sin2(uint64_t x2) {
    uint64_t y2 = fma2(x2, DUP(0.3183098861837907f), DUP(12582912.0f));
    uint64_t sgn = (y2 & 0x0000000100000001ULL) << 31;
    uint64_t k2 = add2(y2, DUP(-12582912.0f));
    uint64_t r2 = fma2(k2, DUP(-3.14159274f), x2);
    r2 = fma2(k2, DUP(8.742277657e-8f), r2);
    uint64_t yy = mul2(r2, r2);
    uint64_t p = fma2(yy, DUP(-2.3889859e-8f), DUP(2.7525562e-6f));
    p = fma2(yy, p, DUP(-1.9840874e-4f));
    p = fma2(yy, p, DUP(8.3333310e-3f));
    p = fma2(yy, p, DUP(-1.6666667e-1f));
    p = fma2(yy, p, DUP(1.0f));
    p = mul2(r2, p);
    return p ^ sgn;
}

// ---------------- one hidden layer: hT(new) = sin(OMEGA*hT@Ws + biasO) ------
// hT: [K rows][MROW pts], Ws: [K rows][HID cols]. biasO holds OMEGA*bias
// (for K=3 it holds OMEGA*(z.W[3:16]+b0), folding the latent term).
// Thread tile: pts {q0..q0+3, q0+128..+131} (f32x2 pairs) x cols col0..col0+7.
// PF=1: after the internal sync, prefetch+dequant NEXT layer's weights+bias.
// Caller must __syncthreads() after return before using Ws/bias_slot.
template<int K, int PF>
__device__ __forceinline__ void layer_gemm_sin(float* hT, float* Ws,
                                               const float* biasO,
                                               int q0, int col0,
                                               const int4* nlab4,
                                               const float* ncent,
                                               const float* nbias,
                                               float* bias_slot, int tid) {
    uint64_t acc[4][8];
#pragma unroll
    for (int p = 0; p < 4; p++)
#pragma unroll
        for (int c = 0; c < 8; c++) acc[p][c] = 0ULL;

#pragma unroll 4
    for (int k = 0; k < K; k++) {
        const float* arow = hT + k * MROW;
        ulonglong2 A0 = *(const ulonglong2*)(arow + q0);        // pts q0..q0+3
        ulonglong2 A1 = *(const ulonglong2*)(arow + q0 + 128);  // pts +128
        uint64_t A[4] = {A0.x, A0.y, A1.x, A1.y};
        const float* brow = Ws + k * HID + col0;
        float4 b0 = *(const float4*)brow;
        float4 b1 = *(const float4*)(brow + 4);
        float bs[8] = {b0.x, b0.y, b0.z, b0.w, b1.x, b1.y, b1.z, b1.w};
#pragma unroll
        for (int c = 0; c < 8; c++) {
            uint64_t bw = pack2(bs[c], bs[c]);
            acc[0][c] = fma2(bw, A[0], acc[0][c]);
            acc[1][c] = fma2(bw, A[1], acc[1][c]);
            acc[2][c] = fma2(bw, A[2], acc[2][c]);
            acc[3][c] = fma2(bw, A[3], acc[3][c]);
        }
    }

    // epilogue: x = OMEGA*acc + biasO (pre-scaled), packed sin (registers only)
    const uint64_t om2 = DUP(OMEGA);
#pragma unroll
    for (int c = 0; c < 8; c++) {
        uint64_t bw = DUP(biasO[col0 + c]);
#pragma unroll
        for (int p = 0; p < 4; p++)
            acc[p][c] = sin2(fma2(om2, acc[p][c], bw));
    }
    __syncthreads();   // all reads of hT/Ws/biasO complete

    // ---- next-layer prefetch: issue label LDGs early (latency hides behind
    // the sin writeback below), gather+store after.
    int4 v[4];
    float nb = 0.0f;
    if (PF) {
#pragma unroll
        for (int j = 0; j < 4; j++) v[j] = nlab4[tid + j * 512];
        if (tid < HID) nb = nbias[tid];
    }

    // writeback first half (cols 0..3)
#pragma unroll
    for (int c = 0; c < 4; c++) {
        float* dst = hT + (col0 + c) * MROW;
        *(ulonglong2*)(dst + q0)       = make_ulonglong2(acc[0][c], acc[1][c]);
        *(ulonglong2*)(dst + q0 + 128) = make_ulonglong2(acc[2][c], acc[3][c]);
    }

    int4 v2[4];
    if (PF) {
#pragma unroll
        for (int j = 0; j < 4; j++) v2[j] = nlab4[tid + (4 + j) * 512];
    }

    // writeback second half (cols 4..7)
#pragma unroll
    for (int c = 4; c < 8; c++) {
        float* dst = hT + (col0 + c) * MROW;
        *(ulonglong2*)(dst + q0)       = make_ulonglong2(acc[0][c], acc[1][c]);
        *(ulonglong2*)(dst + q0 + 128) = make_ulonglong2(acc[2][c], acc[3][c]);
    }

    if (PF) {
        float4* w4 = (float4*)Ws;
#pragma unroll
        for (int j = 0; j < 4; j++) {
            int4 u = v[j];
            float4 w;
            w.x = ncent[u.x]; w.y = ncent[u.y]; w.z = ncent[u.z]; w.w = ncent[u.w];
            w4[tid + j * 512] = w;
        }
#pragma unroll
        for (int j = 0; j < 4; j++) {
            int4 u = v2[j];
            float4 w;
            w.x = ncent[u.x]; w.y = ncent[u.y]; w.z = ncent[u.z]; w.w = ncent[u.w];
            w4[tid + (4 + j) * 512] = w;
        }
        if (tid < HID) bias_slot[tid] = OMEGA * nb;
    }
}

__global__ void __launch_bounds__(THREADS, 1)
ecnr_kernel(const float* __restrict__ x,
            const int* __restrict__ mlp_idx,
            const int* __restrict__ block_idx,
            const float* __restrict__ latent_table,
            const float* __restrict__ cent0, const int* __restrict__ lab0, const float* __restrict__ bias0,
            const float* __restrict__ cent1, const int* __restrict__ lab1, const float* __restrict__ bias1,
            const float* __restrict__ cent2, const int* __restrict__ lab2, const float* __restrict__ bias2,
            const float* __restrict__ cent3, const int* __restrict__ lab3, const float* __restrict__ bias3,
            float* __restrict__ out) {
    extern __shared__ float sm[];
    float* hT = sm;                 // [128][256]
    float* Ws = sm + HT_SZ;         // [128][128]
    float* cs0 = sm + HT_SZ + WS_SZ;
    float* cs1 = cs0 + 256;
    float* cs2 = cs1 + 256;
    float* cs3 = cs2 + 256;
    float* bias_s = cs3 + 256;      // 128 (OMEGA*bias, layers 1-2)
    float* part   = bias_s + 128;   // 512
    float* zwb    = part + 512;     // 128 (OMEGA*(z.W[3:16]+b0))
    float* zsm    = zwb + 128;      // 13 latent values
    float* b3s    = zsm + 16;       // 1

    int tid = threadIdx.x;
    int b   = blockIdx.y;
    int pt0 = blockIdx.x * MROW;
    int mlp = mlp_idx[b];
    int blk = block_idx[b];

    // centroid tables (all 4 layers)
    if (tid < 256) {
        cs0[tid] = cent0[tid];
        cs1[tid] = cent1[tid];
        cs2[tid] = cent2[tid];
        cs3[tid] = cent3[tid];
    }
    if (tid == 0)  b3s[0] = bias3[mlp];
    if (tid < 13)  zsm[tid] = latent_table[((long)mlp * 8 + blk) * 13 + tid];

    // layer-0 input: only 3 coord rows (latent term folded into zwb)
    if (tid < MROW) {
        const float* xp = x + ((long)b * NPTS + pt0 + tid) * 3;
        hT[0 * MROW + tid] = xp[0];
        hT[1 * MROW + tid] = xp[1];
        hT[2 * MROW + tid] = xp[2];
    }

    // layer-0 dequant (512 int4 -> one per thread); issue LDG before sync
    int4 v0 = ((const int4*)(lab0 + mlp * (16 * HID)))[tid];
    float bia0 = (tid < HID) ? bias0[mlp * HID + tid] : 0.0f;
    __syncthreads();            // cs0/zsm/hT visible
    {
        float4 w;
        w.x = cs0[v0.x]; w.y = cs0[v0.y]; w.z = cs0[v0.z]; w.w = cs0[v0.w];
        ((float4*)Ws)[tid] = w;
    }
    __syncthreads();            // Ws (layer 0) ready

    // zwb[c] = OMEGA * (sum_j z_j * W0[3+j][c] + b0[c])   (threads 0..127)
    if (tid < HID) {
        float s = bia0;
#pragma unroll
        for (int j = 0; j < 13; j++)
            s = fmaf(zsm[j], Ws[(3 + j) * HID + tid], s);
        zwb[tid] = OMEGA * s;
    }
    __syncthreads();            // zwb ready

    // 2D tiling indices
    int wid = tid >> 5, lane = tid & 31;
    int lr = lane & 7, lc = lane >> 3;
    int wr = wid & 3, wc = wid >> 2;
    int q0   = wr * 32 + lr * 4;       // point base (pairs q0..q0+3, +128)
    int col0 = wc * 32 + lc * 8;       // 8 columns

    // layer 0: K=3 gemm, "bias" = zwb (carries latent term)
    layer_gemm_sin<3, 1>(hT, Ws, zwb, q0, col0,
                         (const int4*)(lab1 + (long)mlp * (HID * HID)),
                         cs1, bias1 + mlp * HID, bias_s, tid);
    __syncthreads();

    layer_gemm_sin<128, 1>(hT, Ws, bias_s, q0, col0,
                           (const int4*)(lab2 + (long)mlp * (HID * HID)),
                           cs2, bias2 + mlp * HID, bias_s, tid);
    __syncthreads();

    layer_gemm_sin<128, 0>(hT, Ws, bias_s, q0, col0,
                           nullptr, nullptr, nullptr, nullptr, tid);

    // layer-3 weights (128x1)
    if (tid < 32) {
        int4 v = ((const int4*)(lab3 + mlp * HID))[tid];
        float4 w;
        w.x = cs3[v.x]; w.y = cs3[v.y]; w.z = cs3[v.z]; w.w = cs3[v.w];
        ((float4*)Ws)[tid] = w;
    }
    __syncthreads();

    // layer 3: dot over 128 dims, split over 2 halves of k
    {
        int pt = tid & 255, half = tid >> 8;
        float s = 0.0f;
        const float* hp = hT + half * 64 * MROW + pt;
        const float* wp = Ws + half * 64;
#pragma unroll 16
        for (int k = 0; k < 64; k++)
            s = fmaf(hp[k * MROW], wp[k], s);
        part[half * 256 + pt] = s;
    }
    __syncthreads();
    if (tid < MROW) {
        out[(long)b * NPTS + pt0 + tid] = part[tid] + part[256 + tid] + b3s[0];
    }
}

extern "C" void kernel_launch(void* const* d_in, const int* in_sizes, int n_in,
                              void* d_out, int out_size) {
    (void)n_in; (void)out_size;
    cudaFuncSetAttribute(ecnr_kernel,
                         cudaFuncAttributeMaxDynamicSharedMemorySize, SMEM_BYTES);
    int B = in_sizes[1];                 // number of samples (mlp_idx count)
    dim3 grid(NCHUNK, B);
    ecnr_kernel<<<grid, THREADS, SMEM_BYTES>>>(
        (const float*)d_in[0], (const int*)d_in[1], (const int*)d_in[2],
        (const float*)d_in[3],
        (const float*)d_in[4],  (const int*)d_in[5],  (const float*)d_in[6],
        (const float*)d_in[7],  (const int*)d_in[8],  (const float*)d_in[9],
        (const float*)d_in[10], (const int*)d_in[11], (const float*)d_in[12],
        (const float*)d_in[13], (const int*)d_in[14], (const float*)d_in[15],
        (float*)d_out);
}

// round 12
// speedup vs baseline: 1.1385x; 1.0413x over previous
#include <cuda_runtime.h>
#include <cstdint>

#define OMEGA 30.0f
#define HID 128
#define MROW 256          // points per CTA
#define THREADS 512
#define NPTS 2048
#define NCHUNK (NPTS / MROW)

// shared memory layout (in floats)
#define HT_SZ   (HID * MROW)          // 32768 floats (128KB)
#define WS_SZ   (HID * HID)           // 16384 floats (64KB)
#define SMEM_FLOATS (HT_SZ + WS_SZ + 4*256 + 128 + 1024 + 128 + 32)
#define SMEM_BYTES  (SMEM_FLOATS * 4)

// ---------------- packed f32x2 helpers ----------------
__device__ __forceinline__ uint64_t pack2(float lo, float hi) {
    uint64_t r;
    asm("mov.b64 %0, {%1, %2};" : "=l"(r) : "f"(lo), "f"(hi));
    return r;
}
__device__ __forceinline__ float2 unpack2(uint64_t v) {
    float2 f;
    asm("mov.b64 {%0, %1}, %2;" : "=f"(f.x), "=f"(f.y) : "l"(v));
    return f;
}
__device__ __forceinline__ uint64_t fma2(uint64_t a, uint64_t b, uint64_t c) {
    uint64_t d;
    asm("fma.rn.f32x2 %0, %1, %2, %3;" : "=l"(d) : "l"(a), "l"(b), "l"(c));
    return d;
}
__device__ __forceinline__ uint64_t add2(uint64_t a, uint64_t b) {
    uint64_t d;
    asm("add.rn.f32x2 %0, %1, %2;" : "=l"(d) : "l"(a), "l"(b));
    return d;
}
#define DUP(c) pack2((c), (c))

// -------- packed sin via exact CW reduction + MUFU poly (both lanes) --------
// x in radians, |x| < ~1e3. Reduce by pi (2-term Cody-Waite, fma-exact),
// fold parity sign into r (sin odd), then __sinf on the reduced halves
// (|r|<=pi/2 -> MUFU error ~4.8e-7). Poly work moves off the fma pipe.
__device__ __forceinline__ uint64_t sin2(uint64_t x2) {
    uint64_t y2 = fma2(x2, DUP(0.3183098861837907f), DUP(12582912.0f));
    uint64_t sgn = (y2 & 0x0000000100000001ULL) << 31;
    uint64_t k2 = add2(y2, DUP(-12582912.0f));
    uint64_t r2 = fma2(k2, DUP(-3.14159274f), x2);
    r2 = fma2(k2, DUP(8.742277657e-8f), r2);
    r2 ^= sgn;                       // sin(x) = sin((-1)^k r)
    float2 rf = unpack2(r2);
    return pack2(__sinf(rf.x), __sinf(rf.y));
}

// ---------------- one hidden layer: hT(new) = sin(OMEGA*hT@Ws + biasO) ------
// hT: [K rows][MROW pts], Ws: [K rows][HID cols]. biasO holds OMEGA*bias
// (for K=3 it holds OMEGA*(z.W[3:16]+b0), folding the latent term).
// Thread tile: pts {q0..q0+3, q0+128..+131} (f32x2 pairs) x cols col0..col0+7.
// PF=1: after the internal sync, prefetch+dequant NEXT layer's weights+bias.
// Caller must __syncthreads() after return before using Ws/bias_slot.
template<int K, int PF>
__device__ __forceinline__ void layer_gemm_sin(float* hT, float* Ws,
                                               const float* biasO,
                                               int q0, int col0,
                                               const int4* nlab4,
                                               const float* ncent,
                                               const float* nbias,
                                               float* bias_slot, int tid) {
    uint64_t acc[4][8];
#pragma unroll
    for (int p = 0; p < 4; p++)
#pragma unroll
        for (int c = 0; c < 8; c++) acc[p][c] = 0ULL;

#pragma unroll 4
    for (int k = 0; k < K; k++) {
        const float* arow = hT + k * MROW;
        ulonglong2 A0 = *(const ulonglong2*)(arow + q0);        // pts q0..q0+3
        ulonglong2 A1 = *(const ulonglong2*)(arow + q0 + 128);  // pts +128
        uint64_t A[4] = {A0.x, A0.y, A1.x, A1.y};
        const float* brow = Ws + k * HID + col0;
        float4 b0 = *(const float4*)brow;
        float4 b1 = *(const float4*)(brow + 4);
        float bs[8] = {b0.x, b0.y, b0.z, b0.w, b1.x, b1.y, b1.z, b1.w};
#pragma unroll
        for (int c = 0; c < 8; c++) {
            uint64_t bw = pack2(bs[c], bs[c]);
            acc[0][c] = fma2(bw, A[0], acc[0][c]);
            acc[1][c] = fma2(bw, A[1], acc[1][c]);
            acc[2][c] = fma2(bw, A[2], acc[2][c]);
            acc[3][c] = fma2(bw, A[3], acc[3][c]);
        }
    }

    // epilogue: x = OMEGA*acc + biasO (pre-scaled), CW+MUFU sin (registers)
    const uint64_t om2 = DUP(OMEGA);
#pragma unroll
    for (int c = 0; c < 8; c++) {
        uint64_t bw = DUP(biasO[col0 + c]);
#pragma unroll
        for (int p = 0; p < 4; p++)
            acc[p][c] = sin2(fma2(om2, acc[p][c], bw));
    }
    __syncthreads();   // all reads of hT/Ws/biasO complete

    // ---- next-layer prefetch: issue label LDGs early (latency hides behind
    // the sin writeback below), gather+store after.
    int4 v[4];
    float nb = 0.0f;
    if (PF) {
#pragma unroll
        for (int j = 0; j < 4; j++) v[j] = nlab4[tid + j * 512];
        if (tid < HID) nb = nbias[tid];
    }

    // writeback first half (cols 0..3)
#pragma unroll
    for (int c = 0; c < 4; c++) {
        float* dst = hT + (col0 + c) * MROW;
        *(ulonglong2*)(dst + q0)       = make_ulonglong2(acc[0][c], acc[1][c]);
        *(ulonglong2*)(dst + q0 + 128) = make_ulonglong2(acc[2][c], acc[3][c]);
    }

    int4 v2[4];
    if (PF) {
#pragma unroll
        for (int j = 0; j < 4; j++) v2[j] = nlab4[tid + (4 + j) * 512];
    }

    // writeback second half (cols 4..7)
#pragma unroll
    for (int c = 4; c < 8; c++) {
        float* dst = hT + (col0 + c) * MROW;
        *(ulonglong2*)(dst + q0)       = make_ulonglong2(acc[0][c], acc[1][c]);
        *(ulonglong2*)(dst + q0 + 128) = make_ulonglong2(acc[2][c], acc[3][c]);
    }

    if (PF) {
        float4* w4 = (float4*)Ws;
#pragma unroll
        for (int j = 0; j < 4; j++) {
            int4 u = v[j];
            float4 w;
            w.x = ncent[u.x]; w.y = ncent[u.y]; w.z = ncent[u.z]; w.w = ncent[u.w];
            w4[tid + j * 512] = w;
        }
#pragma unroll
        for (int j = 0; j < 4; j++) {
            int4 u = v2[j];
            float4 w;
            w.x = ncent[u.x]; w.y = ncent[u.y]; w.z = ncent[u.z]; w.w = ncent[u.w];
            w4[tid + (4 + j) * 512] = w;
        }
        if (tid < HID) bias_slot[tid] = OMEGA * nb;
    }
}

__global__ void __launch_bounds__(THREADS, 1)
ecnr_kernel(const float* __restrict__ x,
            const int* __restrict__ mlp_idx,
            const int* __restrict__ block_idx,
            const float* __restrict__ latent_table,
            const float* __restrict__ cent0, const int* __restrict__ lab0, const float* __restrict__ bias0,
            const float* __restrict__ cent1, const int* __restrict__ lab1, const float* __restrict__ bias1,
            const float* __restrict__ cent2, const int* __restrict__ lab2, const float* __restrict__ bias2,
            const float* __restrict__ cent3, const int* __restrict__ lab3, const float* __restrict__ bias3,
            float* __restrict__ out) {
    extern __shared__ float sm[];
    float* hT = sm;                 // [128][256]
    float* Ws = sm + HT_SZ;         // [128][128]
    float* cs0 = sm + HT_SZ + WS_SZ;
    float* cs1 = cs0 + 256;
    float* cs2 = cs1 + 256;
    float* cs3 = cs2 + 256;
    float* bias_s = cs3 + 256;      // 128 (OMEGA*bias, layers 1-2)
    float* part   = bias_s + 128;   // 1024 (4 quarters x 128 pairs x 2)
    float* zwb    = part + 1024;    // 128 (OMEGA*(z.W[3:16]+b0))
    float* zsm    = zwb + 128;      // 13 latent values
    float* b3s    = zsm + 16;       // 1

    int tid = threadIdx.x;
    int b   = blockIdx.y;
    int pt0 = blockIdx.x * MROW;
    int mlp = mlp_idx[b];
    int blk = block_idx[b];

    // centroid tables (all 4 layers)
    if (tid < 256) {
        cs0[tid] = cent0[tid];
        cs1[tid] = cent1[tid];
        cs2[tid] = cent2[tid];
        cs3[tid] = cent3[tid];
    }
    if (tid == 0)  b3s[0] = bias3[mlp];
    if (tid < 13)  zsm[tid] = latent_table[((long)mlp * 8 + blk) * 13 + tid];

    // layer-0 input: only 3 coord rows (latent term folded into zwb)
    if (tid < MROW) {
        const float* xp = x + ((long)b * NPTS + pt0 + tid) * 3;
        hT[0 * MROW + tid] = xp[0];
        hT[1 * MROW + tid] = xp[1];
        hT[2 * MROW + tid] = xp[2];
    }

    // layer-0 dequant (512 int4 -> one per thread); issue LDG before sync
    int4 v0 = ((const int4*)(lab0 + mlp * (16 * HID)))[tid];
    float bia0 = (tid < HID) ? bias0[mlp * HID + tid] : 0.0f;
    __syncthreads();            // cs0/zsm/hT visible
    {
        float4 w;
        w.x = cs0[v0.x]; w.y = cs0[v0.y]; w.z = cs0[v0.z]; w.w = cs0[v0.w];
        ((float4*)Ws)[tid] = w;
    }
    __syncthreads();            // Ws (layer 0) ready

    // zwb[c] = OMEGA * (sum_j z_j * W0[3+j][c] + b0[c])   (threads 0..127)
    if (tid < HID) {
        float s = bia0;
#pragma unroll
        for (int j = 0; j < 13; j++)
            s = fmaf(zsm[j], Ws[(3 + j) * HID + tid], s);
        zwb[tid] = OMEGA * s;
    }
    __syncthreads();            // zwb ready

    // 2D tiling indices
    int wid = tid >> 5, lane = tid & 31;
    int lr = lane & 7, lc = lane >> 3;
    int wr = wid & 3, wc = wid >> 2;
    int q0   = wr * 32 + lr * 4;       // point base (pairs q0..q0+3, +128)
    int col0 = wc * 32 + lc * 8;       // 8 columns

    // layer 0: K=3 gemm, "bias" = zwb (carries latent term)
    layer_gemm_sin<3, 1>(hT, Ws, zwb, q0, col0,
                         (const int4*)(lab1 + (long)mlp * (HID * HID)),
                         cs1, bias1 + mlp * HID, bias_s, tid);
    __syncthreads();

    layer_gemm_sin<128, 1>(hT, Ws, bias_s, q0, col0,
                           (const int4*)(lab2 + (long)mlp * (HID * HID)),
                           cs2, bias2 + mlp * HID, bias_s, tid);
    __syncthreads();

    layer_gemm_sin<128, 0>(hT, Ws, bias_s, q0, col0,
                           nullptr, nullptr, nullptr, nullptr, tid);

    // layer-3 weights (128x1)
    if (tid < 32) {
        int4 v = ((const int4*)(lab3 + mlp * HID))[tid];
        float4 w;
        w.x = cs3[v.x]; w.y = cs3[v.y]; w.z = cs3[v.z]; w.w = cs3[v.w];
        ((float4*)Ws)[tid] = w;
    }
    __syncthreads();

    // layer 3: packed dot over 128 dims, split over 4 k-quarters
    {
        int pp = tid & 127, q = tid >> 7;      // point-pair, k-quarter
        uint64_t s2 = 0ULL;
        const float* wp = Ws + q * 32;
        const float* hp = hT + (q * 32) * MROW + 2 * pp;
#pragma unroll 8
        for (int k = 0; k < 32; k++) {
            uint64_t a = *(const uint64_t*)(hp + k * MROW);
            s2 = fma2(DUP(wp[k]), a, s2);
        }
        ((uint64_t*)part)[q * 128 + pp] = s2;
    }
    __syncthreads();
    if (tid < MROW) {
        out[(long)b * NPTS + pt0 + tid] =
            part[tid] + part[256 + tid] + part[512 + tid] + part[768 + tid] + b3s[0];
    }
}

extern "C" void kernel_launch(void* const* d_in, const int* in_sizes, int n_in,
                              void* d_out, int out_size) {
    (void)n_in; (void)out_size;
    cudaFuncSetAttribute(ecnr_kernel,
                         cudaFuncAttributeMaxDynamicSharedMemorySize, SMEM_BYTES);
    int B = in_sizes[1];                 // number of samples (mlp_idx count)
    dim3 grid(NCHUNK, B);
    ecnr_kernel<<<grid, THREADS, SMEM_BYTES>>>(
        (const float*)d_in[0], (const int*)d_in[1], (const int*)d_in[2],
        (const float*)d_in[3],
        (const float*)d_in[4],  (const int*)d_in[5],  (const float*)d_in[6],
        (const float*)d_in[7],  (const int*)d_in[8],  (const float*)d_in[9],
        (const float*)d_in[10], (const int*)d_in[11], (const float*)d_in[12],
        (const float*)d_in[13], (const int*)d_in[14], (const float*)d_in[15],
        (float*)d_out);
}

// round 13
// speedup vs baseline: 1.2036x; 1.0572x over previous
#include <cuda_runtime.h>
#include <cstdint>

#define OMEGA 30.0f
#define HID 128
#define MROW 256          // points per CTA
#define THREADS 512
#define NPTS 2048
#define NCHUNK (NPTS / MROW)

// shared memory layout (in floats)
#define HT_SZ   (HID * MROW)          // 32768 floats (128KB)
#define WS_SZ   (HID * HID)           // 16384 floats (64KB)
#define SMEM_FLOATS (HT_SZ + WS_SZ + 4*256 + 128 + 1024 + 128 + 32)
#define SMEM_BYTES  (SMEM_FLOATS * 4)

// ---------------- packed f32x2 helpers ----------------
__device__ __forceinline__ uint64_t pack2(float lo, float hi) {
    uint64_t r;
    asm("mov.b64 %0, {%1, %2};" : "=l"(r) : "f"(lo), "f"(hi));
    return r;
}
__device__ __forceinline__ float2 unpack2(uint64_t v) {
    float2 f;
    asm("mov.b64 {%0, %1}, %2;" : "=f"(f.x), "=f"(f.y) : "l"(v));
    return f;
}
__device__ __forceinline__ uint64_t fma2(uint64_t a, uint64_t b, uint64_t c) {
    uint64_t d;
    asm("fma.rn.f32x2 %0, %1, %2, %3;" : "=l"(d) : "l"(a), "l"(b), "l"(c));
    return d;
}
__device__ __forceinline__ uint64_t add2(uint64_t a, uint64_t b) {
    uint64_t d;
    asm("add.rn.f32x2 %0, %1, %2;" : "=l"(d) : "l"(a), "l"(b));
    return d;
}
#define DUP(c) pack2((c), (c))

// -------- packed sin via exact CW reduction + MUFU poly (both lanes) --------
__device__ __forceinline__ uint64_t sin2(uint64_t x2) {
    uint64_t y2 = fma2(x2, DUP(0.3183098861837907f), DUP(12582912.0f));
    uint64_t sgn = (y2 & 0x0000000100000001ULL) << 31;
    uint64_t k2 = add2(y2, DUP(-12582912.0f));
    uint64_t r2 = fma2(k2, DUP(-3.14159274f), x2);
    r2 = fma2(k2, DUP(8.742277657e-8f), r2);
    r2 ^= sgn;                       // sin(x) = sin((-1)^k r)
    float2 rf = unpack2(r2);
    return pack2(__sinf(rf.x), __sinf(rf.y));
}

// ---------------- one hidden layer: hT(new) = sin(OMEGA*hT@Ws + biasO) ------
// hT: [K rows][MROW pts], Ws: [K rows][HID cols]. biasO holds OMEGA*bias
// (for K=3 it holds OMEGA*(z.W[3:16]+b0), folding the latent term).
// Thread tile: pts {q0..q0+3, q0+128..+131} (f32x2 pairs) x cols col0..col0+7.
// Inner product ordered p-outer/c-inner so A[p] sits in fma2 slot 0 for runs
// of 8 consecutive instructions (operand-reuse-cache friendly).
// PF=1: after the internal sync, prefetch+dequant NEXT layer's weights+bias.
// Caller must __syncthreads() after return before using Ws/bias_slot.
template<int K, int PF>
__device__ __forceinline__ void layer_gemm_sin(float* hT, float* Ws,
                                               const float* biasO,
                                               int q0, int col0,
                                               const int4* nlab4,
                                               const float* ncent,
                                               const float* nbias,
                                               float* bias_slot, int tid) {
    uint64_t acc[4][8];
#pragma unroll
    for (int p = 0; p < 4; p++)
#pragma unroll
        for (int c = 0; c < 8; c++) acc[p][c] = 0ULL;

#pragma unroll 4
    for (int k = 0; k < K; k++) {
        const float* arow = hT + k * MROW;
        ulonglong2 A0 = *(const ulonglong2*)(arow + q0);        // pts q0..q0+3
        ulonglong2 A1 = *(const ulonglong2*)(arow + q0 + 128);  // pts +128
        uint64_t A[4] = {A0.x, A0.y, A1.x, A1.y};
        const float* brow = Ws + k * HID + col0;
        float4 b0 = *(const float4*)brow;
        float4 b1 = *(const float4*)(brow + 4);
        uint64_t bw[8];
        bw[0] = pack2(b0.x, b0.x); bw[1] = pack2(b0.y, b0.y);
        bw[2] = pack2(b0.z, b0.z); bw[3] = pack2(b0.w, b0.w);
        bw[4] = pack2(b1.x, b1.x); bw[5] = pack2(b1.y, b1.y);
        bw[6] = pack2(b1.z, b1.z); bw[7] = pack2(b1.w, b1.w);
#pragma unroll
        for (int p = 0; p < 4; p++) {
            uint64_t a = A[p];
#pragma unroll
            for (int c = 0; c < 8; c++)
                acc[p][c] = fma2(a, bw[c], acc[p][c]);
        }
    }

    // epilogue: x = OMEGA*acc + biasO (pre-scaled), CW+MUFU sin (registers)
    const uint64_t om2 = DUP(OMEGA);
#pragma unroll
    for (int c = 0; c < 8; c++) {
        uint64_t bw = DUP(biasO[col0 + c]);
#pragma unroll
        for (int p = 0; p < 4; p++)
            acc[p][c] = sin2(fma2(om2, acc[p][c], bw));
    }
    __syncthreads();   // all reads of hT/Ws/biasO complete

    // ---- next-layer prefetch: issue label LDGs early (latency hides behind
    // the sin writeback below), gather+store after.
    int4 v[4];
    float nb = 0.0f;
    if (PF) {
#pragma unroll
        for (int j = 0; j < 4; j++) v[j] = nlab4[tid + j * 512];
        if (tid < HID) nb = nbias[tid];
    }

    // writeback first half (cols 0..3)
#pragma unroll
    for (int c = 0; c < 4; c++) {
        float* dst = hT + (col0 + c) * MROW;
        *(ulonglong2*)(dst + q0)       = make_ulonglong2(acc[0][c], acc[1][c]);
        *(ulonglong2*)(dst + q0 + 128) = make_ulonglong2(acc[2][c], acc[3][c]);
    }

    int4 v2[4];
    if (PF) {
#pragma unroll
        for (int j = 0; j < 4; j++) v2[j] = nlab4[tid + (4 + j) * 512];
    }

    // writeback second half (cols 4..7)
#pragma unroll
    for (int c = 4; c < 8; c++) {
        float* dst = hT + (col0 + c) * MROW;
        *(ulonglong2*)(dst + q0)       = make_ulonglong2(acc[0][c], acc[1][c]);
        *(ulonglong2*)(dst + q0 + 128) = make_ulonglong2(acc[2][c], acc[3][c]);
    }

    if (PF) {
        float4* w4 = (float4*)Ws;
#pragma unroll
        for (int j = 0; j < 4; j++) {
            int4 u = v[j];
            float4 w;
            w.x = ncent[u.x]; w.y = ncent[u.y]; w.z = ncent[u.z]; w.w = ncent[u.w];
            w4[tid + j * 512] = w;
        }
#pragma unroll
        for (int j = 0; j < 4; j++) {
            int4 u = v2[j];
            float4 w;
            w.x = ncent[u.x]; w.y = ncent[u.y]; w.z = ncent[u.z]; w.w = ncent[u.w];
            w4[tid + (4 + j) * 512] = w;
        }
        if (tid < HID) bias_slot[tid] = OMEGA * nb;
    }
}

__global__ void __launch_bounds__(THREADS, 1)
ecnr_kernel(const float* __restrict__ x,
            const int* __restrict__ mlp_idx,
            const int* __restrict__ block_idx,
            const float* __restrict__ latent_table,
            const float* __restrict__ cent0, const int* __restrict__ lab0, const float* __restrict__ bias0,
            const float* __restrict__ cent1, const int* __restrict__ lab1, const float* __restrict__ bias1,
            const float* __restrict__ cent2, const int* __restrict__ lab2, const float* __restrict__ bias2,
            const float* __restrict__ cent3, const int* __restrict__ lab3, const float* __restrict__ bias3,
            float* __restrict__ out) {
    extern __shared__ float sm[];
    float* hT = sm;                 // [128][256]
    float* Ws = sm + HT_SZ;         // [128][128]
    float* cs0 = sm + HT_SZ + WS_SZ;
    float* cs1 = cs0 + 256;
    float* cs2 = cs1 + 256;
    float* cs3 = cs2 + 256;
    float* bias_s = cs3 + 256;      // 128 (OMEGA*bias, layers 1-2)
    float* part   = bias_s + 128;   // 1024 (4 quarters x 128 pairs x 2)
    float* zwb    = part + 1024;    // 128 (OMEGA*(z.W[3:16]+b0))
    float* zsm    = zwb + 128;      // 13 latent values
    float* b3s    = zsm + 16;       // 1

    int tid = threadIdx.x;
    int b   = blockIdx.y;
    int pt0 = blockIdx.x * MROW;
    int mlp = mlp_idx[b];
    int blk = block_idx[b];

    // centroid tables (all 4 layers)
    if (tid < 256) {
        cs0[tid] = cent0[tid];
        cs1[tid] = cent1[tid];
        cs2[tid] = cent2[tid];
        cs3[tid] = cent3[tid];
    }
    if (tid == 0)  b3s[0] = bias3[mlp];
    if (tid < 13)  zsm[tid] = latent_table[((long)mlp * 8 + blk) * 13 + tid];

    // layer-0 input: only 3 coord rows (latent term folded into zwb)
    if (tid < MROW) {
        const float* xp = x + ((long)b * NPTS + pt0 + tid) * 3;
        hT[0 * MROW + tid] = xp[0];
        hT[1 * MROW + tid] = xp[1];
        hT[2 * MROW + tid] = xp[2];
    }

    // layer-0 dequant (512 int4 -> one per thread); issue LDG before sync
    int4 v0 = ((const int4*)(lab0 + mlp * (16 * HID)))[tid];
    float bia0 = (tid < HID) ? bias0[mlp * HID + tid] : 0.0f;
    __syncthreads();            // cs0/zsm/hT visible
    {
        float4 w;
        w.x = cs0[v0.x]; w.y = cs0[v0.y]; w.z = cs0[v0.z]; w.w = cs0[v0.w];
        ((float4*)Ws)[tid] = w;
    }
    __syncthreads();            // Ws (layer 0) ready

    // zwb[c] = OMEGA * (sum_j z_j * W0[3+j][c] + b0[c])   (threads 0..127)
    if (tid < HID) {
        float s = bia0;
#pragma unroll
        for (int j = 0; j < 13; j++)
            s = fmaf(zsm[j], Ws[(3 + j) * HID + tid], s);
        zwb[tid] = OMEGA * s;
    }
    __syncthreads();            // zwb ready

    // 2D tiling indices
    int wid = tid >> 5, lane = tid & 31;
    int lr = lane & 7, lc = lane >> 3;
    int wr = wid & 3, wc = wid >> 2;
    int q0   = wr * 32 + lr * 4;       // point base (pairs q0..q0+3, +128)
    int col0 = wc * 32 + lc * 8;       // 8 columns

    // layer 0: K=3 gemm, "bias" = zwb (carries latent term)
    layer_gemm_sin<3, 1>(hT, Ws, zwb, q0, col0,
                         (const int4*)(lab1 + (long)mlp * (HID * HID)),
                         cs1, bias1 + mlp * HID, bias_s, tid);
    __syncthreads();

    layer_gemm_sin<128, 1>(hT, Ws, bias_s, q0, col0,
                           (const int4*)(lab2 + (long)mlp * (HID * HID)),
                           cs2, bias2 + mlp * HID, bias_s, tid);
    __syncthreads();

    layer_gemm_sin<128, 0>(hT, Ws, bias_s, q0, col0,
                           nullptr, nullptr, nullptr, nullptr, tid);

    // layer-3 weights (128x1)
    if (tid < 32) {
        int4 v = ((const int4*)(lab3 + mlp * HID))[tid];
        float4 w;
        w.x = cs3[v.x]; w.y = cs3[v.y]; w.z = cs3[v.z]; w.w = cs3[v.w];
        ((float4*)Ws)[tid] = w;
    }
    __syncthreads();

    // layer 3: packed dot over 128 dims, split over 4 k-quarters
    {
        int pp = tid & 127, q = tid >> 7;      // point-pair, k-quarter
        uint64_t s2 = 0ULL;
        const float* wp = Ws + q * 32;
        const float* hp = hT + (q * 32) * MROW + 2 * pp;
#pragma unroll 8
        for (int k = 0; k < 32; k++) {
            uint64_t a = *(const uint64_t*)(hp + k * MROW);
            s2 = fma2(DUP(wp[k]), a, s2);
        }
        ((uint64_t*)part)[q * 128 + pp] = s2;
    }
    __syncthreads();
    if (tid < MROW) {
        out[(long)b * NPTS + pt0 + tid] =
            part[tid] + part[256 + tid] + part[512 + tid] + part[768 + tid] + b3s[0];
    }
}

extern "C" void kernel_launch(void* const* d_in, const int* in_sizes, int n_in,
                              void* d_out, int out_size) {
    (void)n_in; (void)out_size;
    cudaFuncSetAttribute(ecnr_kernel,
                         cudaFuncAttributeMaxDynamicSharedMemorySize, SMEM_BYTES);
    int B = in_sizes[1];                 // number of samples (mlp_idx count)
    dim3 grid(NCHUNK, B);
    ecnr_kernel<<<grid, THREADS, SMEM_BYTES>>>(
        (const float*)d_in[0], (const int*)d_in[1], (const int*)d_in[2],
        (const float*)d_in[3],
        (const float*)d_in[4],  (const int*)d_in[5],  (const float*)d_in[6],
        (const float*)d_in[7],  (const int*)d_in[8],  (const float*)d_in[9],
        (const float*)d_in[10], (const int*)d_in[11], (const float*)d_in[12],
        (const float*)d_in[13], (const int*)d_in[14], (const float*)d_in[15],
        (float*)d_out);
}